// round 3
// baseline (speedup 1.0000x reference)
#include <cuda_runtime.h>
#include <cuda_bf16.h>
#include <math.h>

#define NN 50000
#define EE 800000

// ---------------- scratch (static device globals; no runtime alloc) ----------------
__device__ float g_X[(size_t)NN * 64];            // feat@W_enc + b_enc
__device__ float g_X2[(size_t)NN * 256];          // h@W_dec + b_dec
__device__ float g_MLPIN[(size_t)5 * NN * 64];    // slots: h, h_g, shuf_h, sig_neigh, sig_diff
__device__ float g_HID[(size_t)5 * NN * 512];     // mlp hidden
__device__ float g_MLPOUT[(size_t)5 * NN * 64];   // z, z_g, shuf_z, g, g_g
__device__ float g_DEGN[NN];
__device__ float g_DEGD[NN];

// ---------------- GEMM: C[M,Nc] = act(A[M,K] @ W[K,Nc] + bias) ----------------
// BM=128, BN=64, BK=16, 256 threads, 8x4 per thread. ACT: 0=none, 2=prelu(alpha_ptr[0])
template <int ACT>
__global__ void gemm_kernel(const float* __restrict__ A, const float* __restrict__ W,
                            const float* __restrict__ bias, float* __restrict__ C,
                            int M, int K, int Nc, const float* __restrict__ alpha_ptr) {
    __shared__ float As[16][128];
    __shared__ float Ws[16][64];

    const int tid = threadIdx.x;
    const int tx = tid & 15;   // n-group (4 cols)
    const int ty = tid >> 4;   // m-group (8 rows)
    const int bm = blockIdx.y * 128;
    const int bn0 = blockIdx.x * 64;

    const int ar = tid >> 2;   // 0..63 (A tile row within half)
    const int aq = tid & 3;    // 0..3  (A tile k-quad)
    const int wr = tid >> 4;   // 0..15 (W tile k-row)
    const int wq = tid & 15;   // 0..15 (W tile n-quad)

    float acc[8][4];
#pragma unroll
    for (int i = 0; i < 8; i++)
#pragma unroll
        for (int j = 0; j < 4; j++) acc[i][j] = 0.f;

    for (int k0 = 0; k0 < K; k0 += 16) {
        // A tile: 128 rows x 16 cols, transposed into As[k][m]
#pragma unroll
        for (int h = 0; h < 2; h++) {
            int row = bm + ar + h * 64;
            float4 v = make_float4(0.f, 0.f, 0.f, 0.f);
            if (row < M)
                v = *reinterpret_cast<const float4*>(&A[(size_t)row * K + k0 + aq * 4]);
            As[aq * 4 + 0][ar + h * 64] = v.x;
            As[aq * 4 + 1][ar + h * 64] = v.y;
            As[aq * 4 + 2][ar + h * 64] = v.z;
            As[aq * 4 + 3][ar + h * 64] = v.w;
        }
        // W tile: 16 x 64
        {
            float4 v = *reinterpret_cast<const float4*>(&W[(size_t)(k0 + wr) * Nc + bn0 + wq * 4]);
            *reinterpret_cast<float4*>(&Ws[wr][wq * 4]) = v;
        }
        __syncthreads();
#pragma unroll
        for (int kk = 0; kk < 16; kk++) {
            float4 a0 = *reinterpret_cast<const float4*>(&As[kk][ty * 8]);
            float4 a1 = *reinterpret_cast<const float4*>(&As[kk][ty * 8 + 4]);
            float4 b = *reinterpret_cast<const float4*>(&Ws[kk][tx * 4]);
            float am[8] = {a0.x, a0.y, a0.z, a0.w, a1.x, a1.y, a1.z, a1.w};
            float bv[4] = {b.x, b.y, b.z, b.w};
#pragma unroll
            for (int i = 0; i < 8; i++)
#pragma unroll
                for (int j = 0; j < 4; j++) acc[i][j] += am[i] * bv[j];
        }
        __syncthreads();
    }

    float alpha = 0.f;
    if (ACT == 2) alpha = alpha_ptr[0];
    float4 bvec = *reinterpret_cast<const float4*>(&bias[bn0 + tx * 4]);
    float bb[4] = {bvec.x, bvec.y, bvec.z, bvec.w};

#pragma unroll
    for (int i = 0; i < 8; i++) {
        int m = bm + ty * 8 + i;
        if (m < M) {
            float o[4];
#pragma unroll
            for (int j = 0; j < 4; j++) {
                float v = acc[i][j] + bb[j];
                if (ACT == 2) v = (v >= 0.f) ? v : alpha * v;
                o[j] = v;
            }
            *reinterpret_cast<float4*>(&C[(size_t)m * Nc + bn0 + tx * 4]) =
                make_float4(o[0], o[1], o[2], o[3]);
        }
    }
}

// ---------------- SpMM: out[src[e]] += val[e] * X[(perm?)dst[e]] (vector f32x4 red) ---
__global__ void spmm_red_kernel(const int* __restrict__ src, const int* __restrict__ dst,
                                const float* __restrict__ val, const int* __restrict__ perm,
                                const float4* __restrict__ X, float* __restrict__ out,
                                int E, int lc4) {
    unsigned gid = blockIdx.x * blockDim.x + threadIdx.x;
    unsigned e = gid >> lc4;
    if (e >= (unsigned)E) return;
    unsigned C4 = 1u << lc4;
    unsigned c = gid & (C4 - 1);
    int s = src[e];
    int d = dst[e];
    float v = val[e];
    if (perm) d = perm[d];
    float4 x = X[(size_t)d * C4 + c];
    float* p = out + ((size_t)s * C4 + c) * 4;
    asm volatile("red.global.add.v4.f32 [%0], {%1,%2,%3,%4};" ::"l"(p), "f"(v * x.x),
                 "f"(v * x.y), "f"(v * x.z), "f"(v * x.w)
                 : "memory");
}

// ---------------- per-node degree: deg[src[e]] += val[e] ----------------
__global__ void deg_kernel(const int* __restrict__ src, const float* __restrict__ val,
                           float* __restrict__ deg, int E) {
    int e = blockIdx.x * blockDim.x + threadIdx.x;
    if (e < E) atomicAdd(&deg[src[e]], val[e]);
}

// ---------------- elementwise relu (float4) ----------------
__global__ void relu4_kernel(float4* __restrict__ p, int n4) {
    int i = blockIdx.x * blockDim.x + threadIdx.x;
    if (i < n4) {
        float4 v = p[i];
        v.x = fmaxf(v.x, 0.f);
        v.y = fmaxf(v.y, 0.f);
        v.z = fmaxf(v.z, 0.f);
        v.w = fmaxf(v.w, 0.f);
        p[i] = v;
    }
}

// ---------------- in-place sigmoid(buf / max(deg,1)) over [NN,64] ----------------
__global__ void sigavg_kernel(float* __restrict__ buf, const float* __restrict__ deg, int n) {
    int i = blockIdx.x * blockDim.x + threadIdx.x;
    if (i < n) {
        int node = i >> 6;
        float d = deg[node];
        d = (d > 1.f) ? d : 1.f;
        float x = buf[i] / d;
        buf[i] = 1.f / (1.f + expf(-x));
    }
}

// ---------------- discriminator: ret/ret_a = [h_pl . (W c), h_mi . (W c)] + b ------
__global__ void disc_kernel(const float* __restrict__ Mo, const float* __restrict__ W,
                            const float* __restrict__ bptr, float* __restrict__ ret,
                            float* __restrict__ ret_a) {
    __shared__ float Ws[64][65];
    int tid = threadIdx.x;
    for (int i = tid; i < 4096; i += 128) Ws[i >> 6][i & 63] = W[i];
    __syncthreads();

    int warp = tid >> 5, lane = tid & 31;
    int node = blockIdx.x * 4 + warp;
    if (node >= NN) return;

    const float* z = Mo + (size_t)0 * NN * 64 + (size_t)node * 64;
    const float* zg = Mo + (size_t)1 * NN * 64 + (size_t)node * 64;
    const float* sz = Mo + (size_t)2 * NN * 64 + (size_t)node * 64;
    const float* gv = Mo + (size_t)3 * NN * 64 + (size_t)node * 64;
    const float* gg = Mo + (size_t)4 * NN * 64 + (size_t)node * 64;

    float r0 = 0.f, r1 = 0.f, a0 = 0.f, a1 = 0.f;
#pragma unroll
    for (int h = 0; h < 2; h++) {
        int d = lane + h * 32;
        float tgg = 0.f, tg = 0.f;
#pragma unroll
        for (int e = 0; e < 64; e++) {
            float w = Ws[d][e];
            tgg += w * gg[e];
            tg += w * gv[e];
        }
        r0 += z[d] * tgg;
        r1 += sz[d] * tgg;
        a0 += zg[d] * tg;
        a1 += sz[d] * tg;
    }
#pragma unroll
    for (int o = 16; o; o >>= 1) {
        r0 += __shfl_xor_sync(0xFFFFFFFFu, r0, o);
        r1 += __shfl_xor_sync(0xFFFFFFFFu, r1, o);
        a0 += __shfl_xor_sync(0xFFFFFFFFu, a0, o);
        a1 += __shfl_xor_sync(0xFFFFFFFFu, a1, o);
    }
    if (lane == 0) {
        float b = bptr[0];
        ret[(size_t)node * 2 + 0] = r0 + b;
        ret[(size_t)node * 2 + 1] = r1 + b;
        ret_a[(size_t)node * 2 + 0] = a0 + b;
        ret_a[(size_t)node * 2 + 1] = a1 + b;
    }
}

// =====================================================================================
extern "C" void kernel_launch(void* const* d_in, const int* in_sizes, int n_in, void* d_out,
                              int out_size) {
    (void)in_sizes; (void)n_in; (void)out_size;

    const float* feat      = (const float*)d_in[0];
    const int*   adj_src   = (const int*)d_in[1];
    const int*   adj_dst   = (const int*)d_in[2];
    const float* adj_val   = (const float*)d_in[3];
    const int*   gdc_src   = (const int*)d_in[4];
    const int*   gdc_dst   = (const int*)d_in[5];
    const float* gdc_val   = (const float*)d_in[6];
    const int*   neigh_src = (const int*)d_in[7];
    const int*   neigh_dst = (const int*)d_in[8];
    const float* neigh_val = (const float*)d_in[9];
    const int*   diff_src  = (const int*)d_in[10];
    const int*   diff_dst  = (const int*)d_in[11];
    const float* diff_val  = (const float*)d_in[12];
    const int*   perm      = (const int*)d_in[13];
    const float* W_enc     = (const float*)d_in[14];
    const float* b_enc     = (const float*)d_in[15];
    const float* W_dec     = (const float*)d_in[16];
    const float* b_dec     = (const float*)d_in[17];
    const float* W1        = (const float*)d_in[18];
    const float* b1        = (const float*)d_in[19];
    const float* prelu_a   = (const float*)d_in[20];
    const float* W3        = (const float*)d_in[21];
    const float* b3        = (const float*)d_in[22];
    const float* W_disc    = (const float*)d_in[23];
    const float* b_disc    = (const float*)d_in[24];

    float *Xp, *X2p, *MLPINp, *HIDp, *MLPOUTp, *DEGNp, *DEGDp;
    cudaGetSymbolAddress((void**)&Xp, g_X);
    cudaGetSymbolAddress((void**)&X2p, g_X2);
    cudaGetSymbolAddress((void**)&MLPINp, g_MLPIN);
    cudaGetSymbolAddress((void**)&HIDp, g_HID);
    cudaGetSymbolAddress((void**)&MLPOUTp, g_MLPOUT);
    cudaGetSymbolAddress((void**)&DEGNp, g_DEGN);
    cudaGetSymbolAddress((void**)&DEGDp, g_DEGD);

    float* out = (float*)d_out;
    float* emb = out;                              // [NN,256]
    float* ret = out + (size_t)NN * 256;           // [NN,2]
    float* ret_a = ret + (size_t)NN * 2;           // [NN,2]

    // zero accumulators
    cudaMemsetAsync(MLPINp, 0, (size_t)5 * NN * 64 * sizeof(float));
    cudaMemsetAsync(DEGNp, 0, (size_t)NN * sizeof(float));
    cudaMemsetAsync(DEGDp, 0, (size_t)NN * sizeof(float));
    cudaMemsetAsync(emb, 0, (size_t)NN * 256 * sizeof(float));

    // X = feat @ W_enc + b_enc   [NN,64]
    gemm_kernel<0><<<dim3(1, (NN + 127) / 128), 256>>>(feat, W_enc, b_enc, Xp, NN, 256, 64, nullptr);

    // h (slot0), h_g (slot1), shuf_h (slot2): SpMM accumulations (pre-relu)
    {
        unsigned total = (unsigned)EE * 16u;
        unsigned blocks = (total + 255u) / 256u;
        spmm_red_kernel<<<blocks, 256>>>(adj_src, adj_dst, adj_val, nullptr, (const float4*)Xp,
                                         MLPINp + (size_t)0 * NN * 64, EE, 4);
        spmm_red_kernel<<<blocks, 256>>>(gdc_src, gdc_dst, gdc_val, nullptr, (const float4*)Xp,
                                         MLPINp + (size_t)1 * NN * 64, EE, 4);
        spmm_red_kernel<<<blocks, 256>>>(adj_src, adj_dst, adj_val, perm, (const float4*)Xp,
                                         MLPINp + (size_t)2 * NN * 64, EE, 4);
    }
    // relu over slots 0..2
    {
        int n4 = 3 * NN * 64 / 4;
        relu4_kernel<<<(n4 + 255) / 256, 256>>>((float4*)MLPINp, n4);
    }

    // X2 = h @ W_dec + b_dec   [NN,256]
    gemm_kernel<0><<<dim3(4, (NN + 127) / 128), 256>>>(MLPINp, W_dec, b_dec, X2p, NN, 64, 256,
                                                       nullptr);

    // emb = relu(spmm(adj, X2))  directly into d_out
    {
        unsigned total = (unsigned)EE * 64u;
        unsigned blocks = (total + 255u) / 256u;
        spmm_red_kernel<<<blocks, 256>>>(adj_src, adj_dst, adj_val, nullptr, (const float4*)X2p,
                                         emb, EE, 6);
        int n4 = NN * 256 / 4;
        relu4_kernel<<<(n4 + 255) / 256, 256>>>((float4*)emb, n4);
    }

    // degrees
    deg_kernel<<<(EE + 255) / 256, 256>>>(neigh_src, neigh_val, DEGNp, EE);
    deg_kernel<<<(EE + 255) / 256, 256>>>(diff_src, diff_val, DEGDp, EE);

    // sparse averages -> sigmoid, into slots 3 and 4
    {
        unsigned total = (unsigned)EE * 16u;
        unsigned blocks = (total + 255u) / 256u;
        spmm_red_kernel<<<blocks, 256>>>(neigh_src, neigh_dst, neigh_val, nullptr,
                                         (const float4*)MLPINp, MLPINp + (size_t)3 * NN * 64, EE, 4);
        spmm_red_kernel<<<blocks, 256>>>(diff_src, diff_dst, diff_val, nullptr,
                                         (const float4*)(MLPINp + (size_t)1 * NN * 64),
                                         MLPINp + (size_t)4 * NN * 64, EE, 4);
        int n = NN * 64;
        sigavg_kernel<<<(n + 255) / 256, 256>>>(MLPINp + (size_t)3 * NN * 64, DEGNp, n);
        sigavg_kernel<<<(n + 255) / 256, 256>>>(MLPINp + (size_t)4 * NN * 64, DEGDp, n);
    }

    // batched MLP over all 5 inputs: HID = prelu(MLPIN @ W1 + b1), MLPOUT = HID @ W3 + b3
    gemm_kernel<2><<<dim3(8, (5 * NN + 127) / 128), 256>>>(MLPINp, W1, b1, HIDp, 5 * NN, 64, 512,
                                                           prelu_a);
    gemm_kernel<0><<<dim3(1, (5 * NN + 127) / 128), 256>>>(HIDp, W3, b3, MLPOUTp, 5 * NN, 512, 64,
                                                           nullptr);

    // discriminator heads
    disc_kernel<<<(NN + 3) / 4, 128>>>(MLPOUTp, W_disc, b_disc, ret, ret_a);
}

// round 4
// speedup vs baseline: 1.8055x; 1.8055x over previous
#include <cuda_runtime.h>
#include <math.h>

#define NN 50000
#define EE 800000

// ---------------- scratch (static device globals; no runtime alloc) ----------------
__device__ float g_X[(size_t)NN * 64];            // feat@W_enc + b_enc (pre-relu linear)
__device__ float g_S[(size_t)NN * 64];            // spmm(adj, relu_h)  (for emb trick)
__device__ float g_MLPIN[(size_t)5 * NN * 64];    // slots: h, h_g, shuf_h, sig_neigh, sig_diff
__device__ float g_MLPOUT[(size_t)5 * NN * 64];   // z, z_g, shuf_z, g, g_g
__device__ float g_DEGA[NN];
__device__ float g_DEGN[NN];
__device__ float g_DEGD[NN];

// ---------------- tf32 helpers ----------------
__device__ __forceinline__ unsigned cvt_tf32(float x) {
    unsigned u;
    asm("cvt.rna.tf32.f32 %0, %1;" : "=r"(u) : "f"(x));
    return u;
}

__device__ __forceinline__ void mma8(float* c, const unsigned* a, const unsigned* b) {
    asm("mma.sync.aligned.m16n8k8.row.col.f32.tf32.tf32.f32 "
        "{%0,%1,%2,%3},{%4,%5,%6,%7},{%8,%9},{%0,%1,%2,%3};"
        : "+f"(c[0]), "+f"(c[1]), "+f"(c[2]), "+f"(c[3])
        : "r"(a[0]), "r"(a[1]), "r"(a[2]), "r"(a[3]), "r"(b[0]), "r"(b[1]));
}

// ---------------- tf32 GEMM: C[M,Nc] = epi(A[M,K] @ W[K,Nc]) ----------------
// BM=128, BN=64, BK=32, 256 threads (8 warps: 4m x 2n, warp tile 32x32).
// EPI 0: C = acc + bias[n]
// EPI 1: C = relu(acc + deg[m]*bias[n])
template <int EPI>
__global__ __launch_bounds__(256) void mma_gemm(const float* __restrict__ A,
                                                const float* __restrict__ W,
                                                const float* __restrict__ bias,
                                                const float* __restrict__ deg,
                                                float* __restrict__ C, int M, int K, int Nc) {
    __shared__ unsigned As[128][36];  // [m][k], pad 4: frag addr (4*lr+lk) conflict-free
    __shared__ unsigned Bs[32][72];   // [k][n], pad 8: frag addr (8*lk+lr) conflict-free

    const int tid = threadIdx.x, lane = tid & 31, wid = tid >> 5;
    const int bm = blockIdx.y * 128, bn0 = blockIdx.x * 64;
    const int m_base = (wid & 3) * 32, n_base = (wid >> 2) * 32;
    const int lr = lane >> 2, lk = lane & 3;

    float acc[2][4][4];
#pragma unroll
    for (int mi = 0; mi < 2; mi++)
#pragma unroll
        for (int ni = 0; ni < 4; ni++)
#pragma unroll
            for (int i = 0; i < 4; i++) acc[mi][ni][i] = 0.f;

    for (int k0 = 0; k0 < K; k0 += 32) {
        // A tile 128x32
#pragma unroll
        for (int p = 0; p < 4; p++) {
            int idx = tid + p * 256;
            int row = idx >> 3, q = idx & 7;
            float4 v = make_float4(0.f, 0.f, 0.f, 0.f);
            if (bm + row < M)
                v = *reinterpret_cast<const float4*>(A + (size_t)(bm + row) * K + k0 + q * 4);
            As[row][q * 4 + 0] = cvt_tf32(v.x);
            As[row][q * 4 + 1] = cvt_tf32(v.y);
            As[row][q * 4 + 2] = cvt_tf32(v.z);
            As[row][q * 4 + 3] = cvt_tf32(v.w);
        }
        // W tile 32x64
#pragma unroll
        for (int p = 0; p < 2; p++) {
            int idx = tid + p * 256;
            int kr = idx >> 4, q = idx & 15;
            float4 v = *reinterpret_cast<const float4*>(W + (size_t)(k0 + kr) * Nc + bn0 + q * 4);
            Bs[kr][q * 4 + 0] = cvt_tf32(v.x);
            Bs[kr][q * 4 + 1] = cvt_tf32(v.y);
            Bs[kr][q * 4 + 2] = cvt_tf32(v.z);
            Bs[kr][q * 4 + 3] = cvt_tf32(v.w);
        }
        __syncthreads();

#pragma unroll
        for (int kk = 0; kk < 4; kk++) {
            unsigned a[2][4], b[4][2];
#pragma unroll
            for (int mi = 0; mi < 2; mi++) {
                int r0 = m_base + mi * 16 + lr;
                a[mi][0] = As[r0][kk * 8 + lk];
                a[mi][1] = As[r0 + 8][kk * 8 + lk];
                a[mi][2] = As[r0][kk * 8 + lk + 4];
                a[mi][3] = As[r0 + 8][kk * 8 + lk + 4];
            }
#pragma unroll
            for (int ni = 0; ni < 4; ni++) {
                int cn = n_base + ni * 8 + lr;
                b[ni][0] = Bs[kk * 8 + lk][cn];
                b[ni][1] = Bs[kk * 8 + lk + 4][cn];
            }
#pragma unroll
            for (int mi = 0; mi < 2; mi++)
#pragma unroll
                for (int ni = 0; ni < 4; ni++) mma8(acc[mi][ni], a[mi], b[ni]);
        }
        __syncthreads();
    }

    // epilogue
#pragma unroll
    for (int mi = 0; mi < 2; mi++)
#pragma unroll
        for (int ni = 0; ni < 4; ni++)
#pragma unroll
            for (int i = 0; i < 4; i++) {
                int row = m_base + mi * 16 + lr + ((i >= 2) ? 8 : 0);
                int col = n_base + ni * 8 + 2 * lk + (i & 1);
                int gm = bm + row, gn = bn0 + col;
                if (gm < M) {
                    float v = acc[mi][ni][i];
                    if (EPI == 0) {
                        v += bias[gn];
                    } else {
                        v += deg[gm] * bias[gn];
                        v = fmaxf(v, 0.f);
                    }
                    C[(size_t)gm * Nc + gn] = v;
                }
            }
}

// ---------------- fused MLP: C[M,64] = prelu(A[M,64]@W1[64,512]+b1) @ W3[512,64] + b3 -----
// 128-row CTA; hidden processed in 8 chunks of 64 staged through smem (tf32).
__global__ __launch_bounds__(256, 1) void mlp_fused(const float* __restrict__ A,
                                                    const float* __restrict__ W1,
                                                    const float* __restrict__ b1,
                                                    const float* __restrict__ aptr,
                                                    const float* __restrict__ W3,
                                                    const float* __restrict__ b3,
                                                    float* __restrict__ C, int M) {
    extern __shared__ unsigned sm[];
    unsigned(*As)[68] = (unsigned(*)[68])sm;                      // 128x68
    unsigned(*Hs)[68] = (unsigned(*)[68])(sm + 128 * 68);         // 128x68
    unsigned(*W1s)[72] = (unsigned(*)[72])(sm + 2 * 128 * 68);    // 64x72
    unsigned(*W3s)[72] = (unsigned(*)[72])(sm + 2 * 128 * 68 + 64 * 72);

    const int tid = threadIdx.x, lane = tid & 31, wid = tid >> 5;
    const int bm = blockIdx.x * 128;
    const int m_base = (wid & 3) * 32, n_base = (wid >> 2) * 32;
    const int lr = lane >> 2, lk = lane & 3;
    const float alpha = aptr[0];

    // A tile 128x64 (resident for whole kernel)
#pragma unroll
    for (int p = 0; p < 8; p++) {
        int idx = tid + p * 256;
        int row = idx >> 4, q = idx & 15;
        float4 v = make_float4(0.f, 0.f, 0.f, 0.f);
        if (bm + row < M)
            v = *reinterpret_cast<const float4*>(A + (size_t)(bm + row) * 64 + q * 4);
        As[row][q * 4 + 0] = cvt_tf32(v.x);
        As[row][q * 4 + 1] = cvt_tf32(v.y);
        As[row][q * 4 + 2] = cvt_tf32(v.z);
        As[row][q * 4 + 3] = cvt_tf32(v.w);
    }

    float out_acc[2][4][4];
#pragma unroll
    for (int mi = 0; mi < 2; mi++)
#pragma unroll
        for (int ni = 0; ni < 4; ni++)
#pragma unroll
            for (int i = 0; i < 4; i++) out_acc[mi][ni][i] = 0.f;

    for (int ch = 0; ch < 8; ch++) {
        __syncthreads();  // prev chunk's stage2 done (and A-load on first iter)

        // load W1 chunk [64 x 64] and W3 chunk [64 x 64]
#pragma unroll
        for (int p = 0; p < 4; p++) {
            int idx = tid + p * 256;
            int k = idx >> 4, q = idx & 15;
            float4 v1 = *reinterpret_cast<const float4*>(W1 + (size_t)k * 512 + ch * 64 + q * 4);
            W1s[k][q * 4 + 0] = cvt_tf32(v1.x);
            W1s[k][q * 4 + 1] = cvt_tf32(v1.y);
            W1s[k][q * 4 + 2] = cvt_tf32(v1.z);
            W1s[k][q * 4 + 3] = cvt_tf32(v1.w);
            float4 v3 = *reinterpret_cast<const float4*>(W3 + (size_t)(ch * 64 + k) * 64 + q * 4);
            W3s[k][q * 4 + 0] = cvt_tf32(v3.x);
            W3s[k][q * 4 + 1] = cvt_tf32(v3.y);
            W3s[k][q * 4 + 2] = cvt_tf32(v3.z);
            W3s[k][q * 4 + 3] = cvt_tf32(v3.w);
        }
        __syncthreads();

        // stage 1: h = A @ W1chunk
        float h_acc[2][4][4];
#pragma unroll
        for (int mi = 0; mi < 2; mi++)
#pragma unroll
            for (int ni = 0; ni < 4; ni++)
#pragma unroll
                for (int i = 0; i < 4; i++) h_acc[mi][ni][i] = 0.f;

#pragma unroll
        for (int kk = 0; kk < 8; kk++) {
            unsigned a[2][4], b[4][2];
#pragma unroll
            for (int mi = 0; mi < 2; mi++) {
                int r0 = m_base + mi * 16 + lr;
                a[mi][0] = As[r0][kk * 8 + lk];
                a[mi][1] = As[r0 + 8][kk * 8 + lk];
                a[mi][2] = As[r0][kk * 8 + lk + 4];
                a[mi][3] = As[r0 + 8][kk * 8 + lk + 4];
            }
#pragma unroll
            for (int ni = 0; ni < 4; ni++) {
                int cn = n_base + ni * 8 + lr;
                b[ni][0] = W1s[kk * 8 + lk][cn];
                b[ni][1] = W1s[kk * 8 + lk + 4][cn];
            }
#pragma unroll
            for (int mi = 0; mi < 2; mi++)
#pragma unroll
                for (int ni = 0; ni < 4; ni++) mma8(h_acc[mi][ni], a[mi], b[ni]);
        }

        // bias + prelu -> Hs (tf32)
#pragma unroll
        for (int mi = 0; mi < 2; mi++)
#pragma unroll
            for (int ni = 0; ni < 4; ni++)
#pragma unroll
                for (int i = 0; i < 4; i++) {
                    int row = m_base + mi * 16 + lr + ((i >= 2) ? 8 : 0);
                    int col = n_base + ni * 8 + 2 * lk + (i & 1);
                    float v = h_acc[mi][ni][i] + b1[ch * 64 + col];
                    v = (v >= 0.f) ? v : alpha * v;
                    Hs[row][col] = cvt_tf32(v);
                }
        __syncthreads();

        // stage 2: out += H @ W3chunk
#pragma unroll
        for (int kk = 0; kk < 8; kk++) {
            unsigned a[2][4], b[4][2];
#pragma unroll
            for (int mi = 0; mi < 2; mi++) {
                int r0 = m_base + mi * 16 + lr;
                a[mi][0] = Hs[r0][kk * 8 + lk];
                a[mi][1] = Hs[r0 + 8][kk * 8 + lk];
                a[mi][2] = Hs[r0][kk * 8 + lk + 4];
                a[mi][3] = Hs[r0 + 8][kk * 8 + lk + 4];
            }
#pragma unroll
            for (int ni = 0; ni < 4; ni++) {
                int cn = n_base + ni * 8 + lr;
                b[ni][0] = W3s[kk * 8 + lk][cn];
                b[ni][1] = W3s[kk * 8 + lk + 4][cn];
            }
#pragma unroll
            for (int mi = 0; mi < 2; mi++)
#pragma unroll
                for (int ni = 0; ni < 4; ni++) mma8(out_acc[mi][ni], a[mi], b[ni]);
        }
    }

    // epilogue
#pragma unroll
    for (int mi = 0; mi < 2; mi++)
#pragma unroll
        for (int ni = 0; ni < 4; ni++)
#pragma unroll
            for (int i = 0; i < 4; i++) {
                int row = m_base + mi * 16 + lr + ((i >= 2) ? 8 : 0);
                int col = n_base + ni * 8 + 2 * lk + (i & 1);
                int gm = bm + row;
                if (gm < M) C[(size_t)gm * 64 + col] = out_acc[mi][ni][i] + b3[col];
            }
}

// ---------------- SpMM (64 cols): out[src[e]] += val[e] * X[(perm?)dst[e]] --------------
// 8 threads per edge, 8 floats each (2x red.v4).
__global__ void spmm64_kernel(const int* __restrict__ src, const int* __restrict__ dst,
                              const float* __restrict__ val, const int* __restrict__ perm,
                              const float4* __restrict__ X, float* __restrict__ out, int E) {
    unsigned gid = blockIdx.x * blockDim.x + threadIdx.x;
    unsigned e = gid >> 3;
    if (e >= (unsigned)E) return;
    unsigned c = gid & 7;
    int s = src[e];
    int d = dst[e];
    float v = val[e];
    if (perm) d = perm[d];
    const float4* Xr = X + (size_t)d * 16 + c * 2;
    float4 x0 = Xr[0], x1 = Xr[1];
    float* p = out + (size_t)s * 64 + c * 8;
    asm volatile("red.global.add.v4.f32 [%0], {%1,%2,%3,%4};" ::"l"(p), "f"(v * x0.x),
                 "f"(v * x0.y), "f"(v * x0.z), "f"(v * x0.w)
                 : "memory");
    asm volatile("red.global.add.v4.f32 [%0], {%1,%2,%3,%4};" ::"l"(p + 4), "f"(v * x1.x),
                 "f"(v * x1.y), "f"(v * x1.z), "f"(v * x1.w)
                 : "memory");
}

// ---------------- fused degree kernel for 3 graphs ----------------
__global__ void deg3_kernel(const int* __restrict__ sA, const float* __restrict__ vA,
                            const int* __restrict__ sN, const float* __restrict__ vN,
                            const int* __restrict__ sD, const float* __restrict__ vD,
                            float* __restrict__ dA, float* __restrict__ dN,
                            float* __restrict__ dD, int E) {
    int e = blockIdx.x * blockDim.x + threadIdx.x;
    if (e < E) {
        atomicAdd(&dA[sA[e]], vA[e]);
        atomicAdd(&dN[sN[e]], vN[e]);
        atomicAdd(&dD[sD[e]], vD[e]);
    }
}

// ---------------- elementwise relu (float4) ----------------
__global__ void relu4_kernel(float4* __restrict__ p, int n4) {
    int i = blockIdx.x * blockDim.x + threadIdx.x;
    if (i < n4) {
        float4 v = p[i];
        v.x = fmaxf(v.x, 0.f);
        v.y = fmaxf(v.y, 0.f);
        v.z = fmaxf(v.z, 0.f);
        v.w = fmaxf(v.w, 0.f);
        p[i] = v;
    }
}

// ---------------- in-place sigmoid(buf / max(deg,1)) over [NN,64] ----------------
__global__ void sigavg_kernel(float* __restrict__ buf, const float* __restrict__ deg, int n) {
    int i = blockIdx.x * blockDim.x + threadIdx.x;
    if (i < n) {
        int node = i >> 6;
        float d = deg[node];
        d = (d > 1.f) ? d : 1.f;
        float x = buf[i] / d;
        buf[i] = 1.f / (1.f + expf(-x));
    }
}

// ---------------- discriminator ----------------
__global__ void disc_kernel(const float* __restrict__ Mo, const float* __restrict__ W,
                            const float* __restrict__ bptr, float* __restrict__ ret,
                            float* __restrict__ ret_a) {
    __shared__ float Ws[64][65];
    int tid = threadIdx.x;
    for (int i = tid; i < 4096; i += 128) Ws[i >> 6][i & 63] = W[i];
    __syncthreads();

    int warp = tid >> 5, lane = tid & 31;
    int node = blockIdx.x * 4 + warp;
    if (node >= NN) return;

    const float* z = Mo + (size_t)0 * NN * 64 + (size_t)node * 64;
    const float* zg = Mo + (size_t)1 * NN * 64 + (size_t)node * 64;
    const float* sz = Mo + (size_t)2 * NN * 64 + (size_t)node * 64;
    const float* gv = Mo + (size_t)3 * NN * 64 + (size_t)node * 64;
    const float* gg = Mo + (size_t)4 * NN * 64 + (size_t)node * 64;

    float r0 = 0.f, r1 = 0.f, a0 = 0.f, a1 = 0.f;
#pragma unroll
    for (int h = 0; h < 2; h++) {
        int d = lane + h * 32;
        float tgg = 0.f, tg = 0.f;
#pragma unroll
        for (int e = 0; e < 64; e++) {
            float w = Ws[d][e];
            tgg += w * gg[e];
            tg += w * gv[e];
        }
        r0 += z[d] * tgg;
        r1 += sz[d] * tgg;
        a0 += zg[d] * tg;
        a1 += sz[d] * tg;
    }
#pragma unroll
    for (int o = 16; o; o >>= 1) {
        r0 += __shfl_xor_sync(0xFFFFFFFFu, r0, o);
        r1 += __shfl_xor_sync(0xFFFFFFFFu, r1, o);
        a0 += __shfl_xor_sync(0xFFFFFFFFu, a0, o);
        a1 += __shfl_xor_sync(0xFFFFFFFFu, a1, o);
    }
    if (lane == 0) {
        float b = bptr[0];
        ret[(size_t)node * 2 + 0] = r0 + b;
        ret[(size_t)node * 2 + 1] = r1 + b;
        ret_a[(size_t)node * 2 + 0] = a0 + b;
        ret_a[(size_t)node * 2 + 1] = a1 + b;
    }
}

// =====================================================================================
extern "C" void kernel_launch(void* const* d_in, const int* in_sizes, int n_in, void* d_out,
                              int out_size) {
    (void)in_sizes; (void)n_in; (void)out_size;

    const float* feat      = (const float*)d_in[0];
    const int*   adj_src   = (const int*)d_in[1];
    const int*   adj_dst   = (const int*)d_in[2];
    const float* adj_val   = (const float*)d_in[3];
    const int*   gdc_src   = (const int*)d_in[4];
    const int*   gdc_dst   = (const int*)d_in[5];
    const float* gdc_val   = (const float*)d_in[6];
    const int*   neigh_src = (const int*)d_in[7];
    const int*   neigh_dst = (const int*)d_in[8];
    const float* neigh_val = (const float*)d_in[9];
    const int*   diff_src  = (const int*)d_in[10];
    const int*   diff_dst  = (const int*)d_in[11];
    const float* diff_val  = (const float*)d_in[12];
    const int*   perm      = (const int*)d_in[13];
    const float* W_enc     = (const float*)d_in[14];
    const float* b_enc     = (const float*)d_in[15];
    const float* W_dec     = (const float*)d_in[16];
    const float* b_dec     = (const float*)d_in[17];
    const float* W1        = (const float*)d_in[18];
    const float* b1        = (const float*)d_in[19];
    const float* prelu_a   = (const float*)d_in[20];
    const float* W3        = (const float*)d_in[21];
    const float* b3        = (const float*)d_in[22];
    const float* W_disc    = (const float*)d_in[23];
    const float* b_disc    = (const float*)d_in[24];

    float *Xp, *Sp, *MLPINp, *MLPOUTp, *DEGAp, *DEGNp, *DEGDp;
    cudaGetSymbolAddress((void**)&Xp, g_X);
    cudaGetSymbolAddress((void**)&Sp, g_S);
    cudaGetSymbolAddress((void**)&MLPINp, g_MLPIN);
    cudaGetSymbolAddress((void**)&MLPOUTp, g_MLPOUT);
    cudaGetSymbolAddress((void**)&DEGAp, g_DEGA);
    cudaGetSymbolAddress((void**)&DEGNp, g_DEGN);
    cudaGetSymbolAddress((void**)&DEGDp, g_DEGD);

    float* out = (float*)d_out;
    float* emb = out;                       // [NN,256]
    float* ret = out + (size_t)NN * 256;    // [NN,2]
    float* ret_a = ret + (size_t)NN * 2;    // [NN,2]

    // enable large dynamic smem for the fused MLP
    const int MLP_SMEM = (2 * 128 * 68 + 2 * 64 * 72) * 4;  // 106496 bytes
    static bool attr_set = false;
    if (!attr_set) {
        cudaFuncSetAttribute(mlp_fused, cudaFuncAttributeMaxDynamicSharedMemorySize, MLP_SMEM);
        attr_set = true;
    }

    const int MROWS = (NN + 127) / 128;         // 391
    const unsigned spmm_blocks = ((unsigned)EE * 8u + 255u) / 256u;

    // zero accumulators
    cudaMemsetAsync(MLPINp, 0, (size_t)5 * NN * 64 * sizeof(float));
    cudaMemsetAsync(Sp, 0, (size_t)NN * 64 * sizeof(float));
    cudaMemsetAsync(DEGAp, 0, (size_t)NN * sizeof(float));
    cudaMemsetAsync(DEGNp, 0, (size_t)NN * sizeof(float));
    cudaMemsetAsync(DEGDp, 0, (size_t)NN * sizeof(float));

    // degrees (adj deg feeds emb's b_dec term; neigh/diff feed sparse_avg)
    deg3_kernel<<<(EE + 255) / 256, 256>>>(adj_src, adj_val, neigh_src, neigh_val, diff_src,
                                           diff_val, DEGAp, DEGNp, DEGDp, EE);

    // X = feat @ W_enc + b_enc   [NN,64]  (tf32 mma)
    mma_gemm<0><<<dim3(1, MROWS), 256>>>(feat, W_enc, b_enc, nullptr, Xp, NN, 256, 64);

    // h (slot0), h_g (slot1), shuf_h (slot2): SpMM accumulations (pre-relu)
    spmm64_kernel<<<spmm_blocks, 256>>>(adj_src, adj_dst, adj_val, nullptr, (const float4*)Xp,
                                        MLPINp + (size_t)0 * NN * 64, EE);
    spmm64_kernel<<<spmm_blocks, 256>>>(gdc_src, gdc_dst, gdc_val, nullptr, (const float4*)Xp,
                                        MLPINp + (size_t)1 * NN * 64, EE);
    spmm64_kernel<<<spmm_blocks, 256>>>(adj_src, adj_dst, adj_val, perm, (const float4*)Xp,
                                        MLPINp + (size_t)2 * NN * 64, EE);

    // relu over slots 0..2
    {
        int n4 = 3 * NN * 64 / 4;
        relu4_kernel<<<(n4 + 255) / 256, 256>>>((float4*)MLPINp, n4);
    }

    // S = spmm(adj, relu_h)  [NN,64]; then emb = relu(S @ W_dec + deg_adj ⊗ b_dec)
    // (valid because spmm is linear: spmm(adj, h@W+b) = spmm(adj,h)@W + deg⊗b)
    spmm64_kernel<<<spmm_blocks, 256>>>(adj_src, adj_dst, adj_val, nullptr,
                                        (const float4*)MLPINp, Sp, EE);
    mma_gemm<1><<<dim3(4, MROWS), 256>>>(Sp, W_dec, b_dec, DEGAp, emb, NN, 64, 256);

    // sparse averages -> sigmoid, into slots 3 and 4
    spmm64_kernel<<<spmm_blocks, 256>>>(neigh_src, neigh_dst, neigh_val, nullptr,
                                        (const float4*)MLPINp, MLPINp + (size_t)3 * NN * 64, EE);
    spmm64_kernel<<<spmm_blocks, 256>>>(diff_src, diff_dst, diff_val, nullptr,
                                        (const float4*)(MLPINp + (size_t)1 * NN * 64),
                                        MLPINp + (size_t)4 * NN * 64, EE);
    {
        int n = NN * 64;
        sigavg_kernel<<<(n + 255) / 256, 256>>>(MLPINp + (size_t)3 * NN * 64, DEGNp, n);
        sigavg_kernel<<<(n + 255) / 256, 256>>>(MLPINp + (size_t)4 * NN * 64, DEGDp, n);
    }

    // fused batched MLP over all 5 inputs: MLPOUT = prelu(MLPIN@W1+b1)@W3 + b3
    {
        int M = 5 * NN;
        mlp_fused<<<(M + 127) / 128, 256, MLP_SMEM>>>(MLPINp, W1, b1, prelu_a, W3, b3, MLPOUTp, M);
    }

    // discriminator heads
    disc_kernel<<<(NN + 3) / 4, 128>>>(MLPOUTp, W_disc, b_disc, ret, ret_a);
}